// round 4
// baseline (speedup 1.0000x reference)
#include <cuda_runtime.h>
#include <math_constants.h>

// Problem constants
#define B_    16
#define S_    20
#define SP    32            // sessions padded per batch row (for clean 128-row tiles)
#define T_    1280
#define H_    768
#define NI    50000
#define MP    (B_ * SP)     // 512 padded M
#define TEMP_ 0.05f
#define EPS_  1e-8f

// GEMM tiling
#define BM 128
#define BN 128
#define BK 16
#define ASTRIDE (BM + 4)    // smem row pad: stride 132 floats (16B-aligned, conflict-reduced)

// Scratch (device globals: no allocation allowed in kernel_launch)
__device__ float g_A[MP * H_];     // pooled, normalized, /TEMP, b-major padded rows
__device__ float g_valid[MP];      // 1.0 if item present, else 0.0
__device__ float g_inv_en[NI];     // 1 / max(||emb_n||, eps)

// ---------------------------------------------------------------------------
// Kernel 1: per-(b,s) pooling + normalization. grid = 512 blocks, 256 threads.
// ---------------------------------------------------------------------------
__global__ void pool_kernel(const float* __restrict__ hidden,
                            const int*   __restrict__ pos) {
    int blk = blockIdx.x;
    int b = blk >> 5;
    int s = blk & 31;
    int tid = threadIdx.x;

    if (s >= S_) {                       // padded session slot: zero row
        for (int h = tid; h < H_; h += 256) g_A[(size_t)blk * H_ + h] = 0.f;
        if (tid == 0) g_valid[blk] = 0.f;
        return;
    }

    __shared__ int   sp[T_];
    __shared__ float red[8];
    __shared__ int   scount;

    for (int t = tid; t < T_; t += 256) sp[t] = pos[b * T_ + t];
    if (tid == 0) scount = 0;
    __syncthreads();

    const int target = s + 1;

    // count matching tokens
    int cnt = 0;
    for (int t = tid; t < T_; t += 256) cnt += (sp[t] == target);
    #pragma unroll
    for (int o = 16; o; o >>= 1) cnt += __shfl_down_sync(0xffffffffu, cnt, o);
    if ((tid & 31) == 0) atomicAdd(&scount, cnt);
    __syncthreads();
    const int count = scount;

    // sum matching rows; each thread owns 3 hidden columns
    float a0 = 0.f, a1 = 0.f, a2 = 0.f;
    const float* hb = hidden + (size_t)b * T_ * H_;
    for (int t = 0; t < T_; t++) {
        if (sp[t] == target) {
            const float* row = hb + (size_t)t * H_;
            a0 += row[tid];
            a1 += row[tid + 256];
            a2 += row[tid + 512];
        }
    }
    const float inv_c = 1.f / (float)max(count, 1);
    a0 *= inv_c; a1 *= inv_c; a2 *= inv_c;

    // block-reduce sum of squares
    float ss = a0 * a0 + a1 * a1 + a2 * a2;
    #pragma unroll
    for (int o = 16; o; o >>= 1) ss += __shfl_down_sync(0xffffffffu, ss, o);
    if ((tid & 31) == 0) red[tid >> 5] = ss;
    __syncthreads();
    if (tid < 8) {
        float v = red[tid];
        #pragma unroll
        for (int o = 4; o; o >>= 1) v += __shfl_down_sync(0xffu, v, o);
        if (tid == 0) red[0] = v;
    }
    __syncthreads();

    const float nrm = sqrtf(red[0]);
    float scale = 1.f / (fmaxf(nrm, EPS_) * TEMP_);
    if (count == 0) scale = 0.f;

    size_t base = (size_t)blk * H_;
    g_A[base + tid]       = a0 * scale;
    g_A[base + tid + 256] = a1 * scale;
    g_A[base + tid + 512] = a2 * scale;
    if (tid == 0) g_valid[blk] = (count > 0) ? 1.f : 0.f;
}

// ---------------------------------------------------------------------------
// Kernel 2: inverse catalog norms. One warp per item row.
// ---------------------------------------------------------------------------
__global__ void norm_kernel(const float* __restrict__ emb) {
    int n = blockIdx.x * 8 + (threadIdx.x >> 5);
    if (n >= NI) return;
    int lane = threadIdx.x & 31;
    const float* row = emb + (size_t)n * H_;
    float ss = 0.f;
    #pragma unroll 4
    for (int i = lane; i < H_; i += 32) { float v = row[i]; ss += v * v; }
    #pragma unroll
    for (int o = 16; o; o >>= 1) ss += __shfl_down_sync(0xffffffffu, ss, o);
    if (lane == 0) g_inv_en[n] = 1.f / fmaxf(sqrtf(ss), EPS_);
}

// ---------------------------------------------------------------------------
// Kernel 3: fp32 tiled GEMM (A[512,768] x E^T[768,50000]) + fused maxsim.
// BM=128 (4 sessions x 32 padded rows), BN=128, BK=16, 8x8 per thread.
// ---------------------------------------------------------------------------
__global__ __launch_bounds__(256, 2)
void gemm_kernel(const float* __restrict__ emb, float* __restrict__ out) {
    __shared__ float As[BK][ASTRIDE];
    __shared__ float Bs[BK][ASTRIDE];
    __shared__ float invEn[BN];
    __shared__ float validf[BM];
    __shared__ float red[16][BN];

    const int tid = threadIdx.x;
    const int tx = tid & 15;
    const int ty = tid >> 4;
    const int n0 = blockIdx.x * BN;
    const int m0 = blockIdx.y * BM;

    if (tid < BN) {
        int n = n0 + tid;
        invEn[tid]  = (n < NI) ? g_inv_en[n] : 0.f;
        validf[tid] = g_valid[m0 + tid];
    }

    float acc[8][8];
    #pragma unroll
    for (int i = 0; i < 8; i++)
        #pragma unroll
        for (int j = 0; j < 8; j++) acc[i][j] = 0.f;

    for (int kt = 0; kt < H_; kt += BK) {
        __syncthreads();
        #pragma unroll
        for (int p = 0; p < 2; p++) {
            int idx = tid + p * 256;         // 0..511 float4 slots
            int r = idx >> 2;                // tile row 0..127
            int c = idx & 3;                 // k-group
            float4 av = *(const float4*)&g_A[(size_t)(m0 + r) * H_ + kt + c * 4];
            int n = n0 + r;
            float4 bv = make_float4(0.f, 0.f, 0.f, 0.f);
            if (n < NI) bv = *(const float4*)&emb[(size_t)n * H_ + kt + c * 4];
            As[c * 4 + 0][r] = av.x; As[c * 4 + 1][r] = av.y;
            As[c * 4 + 2][r] = av.z; As[c * 4 + 3][r] = av.w;
            Bs[c * 4 + 0][r] = bv.x; Bs[c * 4 + 1][r] = bv.y;
            Bs[c * 4 + 2][r] = bv.z; Bs[c * 4 + 3][r] = bv.w;
        }
        __syncthreads();
        #pragma unroll
        for (int k = 0; k < BK; k++) {
            float4 A0 = *(const float4*)&As[k][ty * 8];
            float4 A1 = *(const float4*)&As[k][ty * 8 + 4];
            float4 B0 = *(const float4*)&Bs[k][tx * 8];
            float4 B1 = *(const float4*)&Bs[k][tx * 8 + 4];
            float a[8] = {A0.x, A0.y, A0.z, A0.w, A1.x, A1.y, A1.z, A1.w};
            float bb[8] = {B0.x, B0.y, B0.z, B0.w, B1.x, B1.y, B1.z, B1.w};
            #pragma unroll
            for (int i = 0; i < 8; i++)
                #pragma unroll
                for (int j = 0; j < 8; j++)
                    acc[i][j] = fmaf(a[i], bb[j], acc[i][j]);
        }
    }
    __syncthreads();

    // Epilogue: scale by inv ||e_n||, mask invalid rows, max over rows per thread
    #pragma unroll
    for (int j = 0; j < 8; j++) {
        float ie = invEn[tx * 8 + j];
        float m = -CUDART_INF_F;
        #pragma unroll
        for (int i = 0; i < 8; i++) {
            float v = acc[i][j] * ie;
            v = (validf[ty * 8 + i] > 0.5f) ? v : -CUDART_INF_F;
            m = fmaxf(m, v);
        }
        red[ty][tx * 8 + j] = m;
    }
    __syncthreads();

    // Combine the 4 ty-slices per 32-row session group; one group == one b
    #pragma unroll
    for (int p = 0; p < 2; p++) {
        int o = tid + p * 256;         // 0..511 outputs (4 groups x 128 cols)
        int g = o >> 7;
        int j = o & 127;
        float sc = fmaxf(fmaxf(red[4 * g + 0][j], red[4 * g + 1][j]),
                         fmaxf(red[4 * g + 2][j], red[4 * g + 3][j]));
        int b = blockIdx.y * 4 + g;
        int n = n0 + j;
        if (n < NI) out[(size_t)b * NI + n] = sc;
    }
}

// ---------------------------------------------------------------------------
// Launch
// ---------------------------------------------------------------------------
extern "C" void kernel_launch(void* const* d_in, const int* in_sizes, int n_in,
                              void* d_out, int out_size) {
    const float* hidden = (const float*)d_in[0];   // [16,1280,768] f32
    const float* emb    = (const float*)d_in[1];   // [50000,768] f32
    const int*   pos    = (const int*)  d_in[3];   // [16,1280] i32
    float* out = (float*)d_out;                    // [16,50000] f32

    pool_kernel<<<MP, 256>>>(hidden, pos);
    norm_kernel<<<(NI + 7) / 8, 256>>>(emb);
    gemm_kernel<<<dim3((NI + BN - 1) / BN, MP / BM), 256>>>(emb, out);
}

// round 6
// speedup vs baseline: 2.7269x; 2.7269x over previous
#include <cuda_runtime.h>
#include <cuda_bf16.h>
#include <math_constants.h>
#include <cstdint>

// ---------------- Problem constants ----------------
#define B_    16
#define S_    20
#define SP    32
#define T_    1280
#define H_    768
#define NI    50000
#define NP    50048            // N padded to multiple of 128
#define MP    (B_ * SP)        // 512 padded M rows (b-major, 32 per b)
#define TEMP_ 0.05f
#define EPS_  1e-8f

// ---------------- GEMM config ----------------
#define BM 128
#define BN 128
#define BK 64
#define NSTAGE 2
#define NKCH (H_ / BK)          // 12
#define TILE_B   16384          // one 128x64 bf16 tile (128 rows x 128B)
#define STAGE_B  (4 * TILE_B)   // Ahi, Alo, Ehi, Elo
#define DSMEM_BYTES (NSTAGE * STAGE_B + 1024)

// ---------------- Scratch (device globals) ----------------
__device__ __nv_bfloat16 g_Ahi[(size_t)MP * H_];
__device__ __nv_bfloat16 g_Alo[(size_t)MP * H_];
__device__ __nv_bfloat16 g_Ehi[(size_t)NP * H_];
__device__ __nv_bfloat16 g_Elo[(size_t)NP * H_];
__device__ float         g_invEn[NP];
__device__ float         g_valid[MP];

// ---------------- helpers ----------------
static __device__ __forceinline__ uint32_t smem_u32(const void* p) {
    uint32_t a;
    asm("{ .reg .u64 t; cvta.to.shared.u64 t, %1; cvt.u32.u64 %0, t; }" : "=r"(a) : "l"(p));
    return a;
}
static __device__ __forceinline__ uint32_t sw128(uint32_t o) { return o ^ ((o >> 3) & 0x70); }

static __device__ __forceinline__ void cp16(uint32_t dst, const void* src) {
    asm volatile("cp.async.cg.shared.global [%0], [%1], 16;" :: "r"(dst), "l"(src));
}
#define CP_COMMIT()   asm volatile("cp.async.commit_group;" ::: "memory")
#define CP_WAIT(n)    asm volatile("cp.async.wait_group %0;" :: "n"(n) : "memory")

static __device__ __forceinline__ void ldsm_x4(uint32_t* r, uint32_t addr) {
    asm volatile("ldmatrix.sync.aligned.m8n8.x4.shared.b16 {%0,%1,%2,%3}, [%4];"
        : "=r"(r[0]), "=r"(r[1]), "=r"(r[2]), "=r"(r[3]) : "r"(addr));
}
static __device__ __forceinline__ void mma16816(float* d, const uint32_t* a, const uint32_t* b) {
    asm volatile("mma.sync.aligned.m16n8k16.row.col.f32.bf16.bf16.f32 "
        "{%0,%1,%2,%3}, {%4,%5,%6,%7}, {%8,%9}, {%0,%1,%2,%3};"
        : "+f"(d[0]), "+f"(d[1]), "+f"(d[2]), "+f"(d[3])
        : "r"(a[0]), "r"(a[1]), "r"(a[2]), "r"(a[3]), "r"(b[0]), "r"(b[1]));
}
static __device__ __forceinline__ unsigned f2o(float x) {
    unsigned u = __float_as_uint(x);
    return (u >> 31) ? ~u : (u | 0x80000000u);
}
static __device__ __forceinline__ float o2f(unsigned u) {
    return (u >> 31) ? __uint_as_float(u & 0x7fffffffu) : __uint_as_float(~u);
}

// ---------------------------------------------------------------------------
// Kernel 1: pooling -> bf16 hi/lo A + validity. grid=512 blocks, 256 threads.
// Item s's tokens occupy the contiguous range [s*64, s*64+64) (or none).
// ---------------------------------------------------------------------------
__global__ void pool_kernel(const float* __restrict__ hidden,
                            const int*   __restrict__ pos) {
    const int blk = blockIdx.x;
    const int b = blk >> 5, s = blk & 31;
    const int tid = threadIdx.x;

    uint32_t* ahr = (uint32_t*)&g_Ahi[(size_t)blk * H_];
    uint32_t* alr = (uint32_t*)&g_Alo[(size_t)blk * H_];

    if (s >= S_) {
        #pragma unroll
        for (int k = 0; k < 2; k++) {
            int i = tid + k * 256;
            if (i < H_ / 2) { ahr[i] = 0u; alr[i] = 0u; }
        }
        if (tid == 0) g_valid[blk] = 0.f;
        return;
    }

    __shared__ int   spos[64];
    __shared__ float red[8];
    if (tid < 64) spos[tid] = pos[b * T_ + s * 64 + tid];
    __syncthreads();

    const int target = s + 1;
    int cnt = 0;
    #pragma unroll 8
    for (int t = 0; t < 64; t++) cnt += (spos[t] == target);

    if (cnt == 0) {
        #pragma unroll
        for (int k = 0; k < 2; k++) {
            int i = tid + k * 256;
            if (i < H_ / 2) { ahr[i] = 0u; alr[i] = 0u; }
        }
        if (tid == 0) g_valid[blk] = 0.f;
        return;
    }

    const float* hb = hidden + ((size_t)b * T_ + (size_t)s * 64) * H_;
    float a0 = 0.f, a1 = 0.f, a2 = 0.f;
    #pragma unroll 4
    for (int t = 0; t < 64; t++) {
        float m = (spos[t] == target) ? 1.f : 0.f;
        const float* r = hb + (size_t)t * H_;
        a0 += m * r[tid];
        a1 += m * r[tid + 256];
        a2 += m * r[tid + 512];
    }
    const float inv_c = 1.f / (float)cnt;
    a0 *= inv_c; a1 *= inv_c; a2 *= inv_c;

    float ss = a0 * a0 + a1 * a1 + a2 * a2;
    #pragma unroll
    for (int o = 16; o; o >>= 1) ss += __shfl_down_sync(0xffffffffu, ss, o);
    if ((tid & 31) == 0) red[tid >> 5] = ss;
    __syncthreads();
    if (tid < 8) {
        float v = red[tid];
        #pragma unroll
        for (int o = 4; o; o >>= 1) v += __shfl_down_sync(0xffu, v, o);
        if (tid == 0) red[0] = v;
    }
    __syncthreads();

    const float scale = 1.f / (fmaxf(sqrtf(red[0]), EPS_) * TEMP_);

    float vals[3] = { a0 * scale, a1 * scale, a2 * scale };
    #pragma unroll
    for (int k = 0; k < 3; k++) {
        int c = tid + k * 256;
        float x = vals[k];
        __nv_bfloat16 h = __float2bfloat16_rn(x);
        __nv_bfloat16 l = __float2bfloat16_rn(x - __bfloat162float(h));
        g_Ahi[(size_t)blk * H_ + c] = h;
        g_Alo[(size_t)blk * H_ + c] = l;
    }
    if (tid == 0) g_valid[blk] = 1.f;
}

// ---------------------------------------------------------------------------
// Kernel 2: E fp32 -> bf16 hi/lo + inverse norms. One warp per row.
// ---------------------------------------------------------------------------
__global__ void eprep_kernel(const float* __restrict__ emb) {
    const int n = blockIdx.x * 8 + (threadIdx.x >> 5);
    const int lane = threadIdx.x & 31;
    if (n >= NP) return;

    uint2* hrow = (uint2*)&g_Ehi[(size_t)n * H_];
    uint2* lrow = (uint2*)&g_Elo[(size_t)n * H_];

    if (n >= NI) {
        #pragma unroll
        for (int u = 0; u < 6; u++) {
            int i = u * 32 + lane;
            hrow[i] = make_uint2(0u, 0u);
            lrow[i] = make_uint2(0u, 0u);
        }
        if (lane == 0) g_invEn[n] = 0.f;
        return;
    }

    const float4* erow = (const float4*)&emb[(size_t)n * H_];
    float ssq = 0.f;
    #pragma unroll
    for (int u = 0; u < 6; u++) {
        int i = u * 32 + lane;
        float4 x = erow[i];
        ssq += x.x * x.x + x.y * x.y + x.z * x.z + x.w * x.w;
        __nv_bfloat16 h0 = __float2bfloat16_rn(x.x);
        __nv_bfloat16 h1 = __float2bfloat16_rn(x.y);
        __nv_bfloat16 h2 = __float2bfloat16_rn(x.z);
        __nv_bfloat16 h3 = __float2bfloat16_rn(x.w);
        __nv_bfloat16 l0 = __float2bfloat16_rn(x.x - __bfloat162float(h0));
        __nv_bfloat16 l1 = __float2bfloat16_rn(x.y - __bfloat162float(h1));
        __nv_bfloat16 l2 = __float2bfloat16_rn(x.z - __bfloat162float(h2));
        __nv_bfloat16 l3 = __float2bfloat16_rn(x.w - __bfloat162float(h3));
        __nv_bfloat162 hp0(h0, h1), hp1(h2, h3), lp0(l0, l1), lp1(l2, l3);
        hrow[i] = make_uint2(*(uint32_t*)&hp0, *(uint32_t*)&hp1);
        lrow[i] = make_uint2(*(uint32_t*)&lp0, *(uint32_t*)&lp1);
    }
    #pragma unroll
    for (int o = 16; o; o >>= 1) ssq += __shfl_down_sync(0xffffffffu, ssq, o);
    if (lane == 0) g_invEn[n] = 1.f / fmaxf(sqrtf(ssq), EPS_);
}

// ---------------------------------------------------------------------------
// Kernel 3: bf16 mma.sync GEMM + fused maxsim epilogue.
// grid = (NP/128, MP/128), 256 threads (8 warps, 2x4 of m64n32 warp tiles).
// ---------------------------------------------------------------------------
__global__ __launch_bounds__(256, 1)
void gemm_mma(float* __restrict__ out) {
    extern __shared__ __align__(16) char dsm[];
    __shared__ unsigned s_red[4][BN];
    __shared__ float s_inv[BN];
    __shared__ float s_val[BM];

    const int tid  = threadIdx.x;
    const int wid  = tid >> 5;
    const int lane = tid & 31;
    const int wm   = wid >> 2;        // 0..1  (m64 tile)
    const int wn   = wid & 3;         // 0..3  (n32 tile)
    const int n0   = blockIdx.x * BN;
    const int m0   = blockIdx.y * BM;

    const uint32_t base = (smem_u32(dsm) + 1023u) & ~1023u;
    const unsigned NEG = f2o(-CUDART_INF_F);

    // epilogue tables + reduction buffer init
    if (tid < BN) s_inv[tid] = g_invEn[n0 + tid];
    if (tid < BM) s_val[tid] = g_valid[m0 + tid];
    #pragma unroll
    for (int k = 0; k < 2; k++) {
        int i = tid + k * 256;
        s_red[i >> 7][i & 127] = NEG;
    }

    // ---- stage loads: 4 tiles of 1024 16B-chunks each ----
    auto issue_loads = [&](int kc, int stg) {
        const uint32_t sb = base + stg * STAGE_B;
        const __nv_bfloat16* srcs[4] = {
            g_Ahi + (size_t)m0 * H_, g_Alo + (size_t)m0 * H_,
            g_Ehi + (size_t)n0 * H_, g_Elo + (size_t)n0 * H_ };
        #pragma unroll
        for (int t = 0; t < 4; t++) {
            const uint32_t tb = sb + t * TILE_B;
            const __nv_bfloat16* src = srcs[t];
            #pragma unroll
            for (int j = 0; j < 4; j++) {
                int i = tid + j * 256;        // 0..1023
                int row = i >> 3, u = i & 7;
                cp16(tb + sw128((uint32_t)(row * 128 + u * 16)),
                     src + (size_t)row * H_ + kc * BK + u * 8);
            }
        }
        CP_COMMIT();
    };

    float acc[4][4][4];
    #pragma unroll
    for (int mi = 0; mi < 4; mi++)
        #pragma unroll
        for (int ni = 0; ni < 4; ni++)
            #pragma unroll
            for (int q = 0; q < 4; q++) acc[mi][ni][q] = 0.f;

    // per-lane ldmatrix row offsets (bytes), within a tile
    const uint32_t a_row = (uint32_t)(wm * 64 + ((lane >> 3) & 1) * 8 + (lane & 7)) * 128;
    const uint32_t a_u   = (uint32_t)((lane >> 4) & 1) * 16;
    const uint32_t b_row = (uint32_t)(wn * 32 + ((lane >> 4) & 1) * 8 + (lane & 7)) * 128;
    const uint32_t b_u   = (uint32_t)((lane >> 3) & 1) * 16;

    issue_loads(0, 0);

    for (int kc = 0; kc < NKCH; kc++) {
        if (kc + 1 < NKCH) { issue_loads(kc + 1, (kc + 1) & 1); CP_WAIT(1); }
        else               { CP_WAIT(0); }
        __syncthreads();

        const uint32_t sb  = base + (kc & 1) * STAGE_B;
        const uint32_t Ahs = sb;
        const uint32_t Als = sb + TILE_B;
        const uint32_t Ehs = sb + 2 * TILE_B;
        const uint32_t Els = sb + 3 * TILE_B;

        #pragma unroll
        for (int s = 0; s < 4; s++) {
            const uint32_t ku = (uint32_t)(s * 32);
            uint32_t ah[4][4], al[4][4], bh[2][4], bl[2][4];
            #pragma unroll
            for (int mi = 0; mi < 4; mi++) {
                uint32_t off = sw128(a_row + (uint32_t)(mi * 16 * 128) + ku + a_u);
                ldsm_x4(ah[mi], Ahs + off);
                ldsm_x4(al[mi], Als + off);
            }
            #pragma unroll
            for (int nj = 0; nj < 2; nj++) {
                uint32_t off = sw128(b_row + (uint32_t)(nj * 16 * 128) + ku + b_u);
                ldsm_x4(bh[nj], Ehs + off);
                ldsm_x4(bl[nj], Els + off);
            }
            #pragma unroll
            for (int mi = 0; mi < 4; mi++)
                #pragma unroll
                for (int ni = 0; ni < 4; ni++) {
                    mma16816(acc[mi][ni], ah[mi], &bh[ni >> 1][(ni & 1) * 2]);
                    mma16816(acc[mi][ni], al[mi], &bh[ni >> 1][(ni & 1) * 2]);
                    mma16816(acc[mi][ni], ah[mi], &bl[ni >> 1][(ni & 1) * 2]);
                }
        }
        __syncthreads();
    }

    // ---- epilogue: scale, mask, 32-row session max via smem atomicMax ----
    #pragma unroll
    for (int mi = 0; mi < 4; mi++) {
        const int r0 = wm * 64 + mi * 16 + (lane >> 2);
        const bool ok0 = s_val[r0]     > 0.5f;
        const bool ok1 = s_val[r0 + 8] > 0.5f;
        const int g = wm * 2 + (mi >> 1);
        #pragma unroll
        for (int ni = 0; ni < 4; ni++) {
            const int c = wn * 32 + ni * 8 + (lane & 3) * 2;
            const float ie0 = s_inv[c], ie1 = s_inv[c + 1];
            unsigned u0 = ok0 ? f2o(acc[mi][ni][0] * ie0) : NEG;
            unsigned u1 = ok0 ? f2o(acc[mi][ni][1] * ie1) : NEG;
            unsigned u2 = ok1 ? f2o(acc[mi][ni][2] * ie0) : NEG;
            unsigned u3 = ok1 ? f2o(acc[mi][ni][3] * ie1) : NEG;
            unsigned m0v = u0 > u2 ? u0 : u2;
            unsigned m1v = u1 > u3 ? u1 : u3;
            atomicMax(&s_red[g][c], m0v);
            atomicMax(&s_red[g][c + 1], m1v);
        }
    }
    __syncthreads();

    #pragma unroll
    for (int k = 0; k < 2; k++) {
        int i = tid + k * 256;             // 0..511
        int g = i >> 7, c = i & 127;
        int n = n0 + c;
        if (n < NI) {
            int b = blockIdx.y * 4 + g;
            out[(size_t)b * NI + n] = o2f(s_red[g][c]);
        }
    }
}

// ---------------------------------------------------------------------------
// Launch
// ---------------------------------------------------------------------------
extern "C" void kernel_launch(void* const* d_in, const int* in_sizes, int n_in,
                              void* d_out, int out_size) {
    const float* hidden = (const float*)d_in[0];   // [16,1280,768] f32
    const float* emb    = (const float*)d_in[1];   // [50000,768] f32
    const int*   pos    = (const int*)  d_in[3];   // [16,1280] i32
    float* out = (float*)d_out;                    // [16,50000] f32

    cudaFuncSetAttribute(gemm_mma, cudaFuncAttributeMaxDynamicSharedMemorySize, DSMEM_BYTES);

    pool_kernel<<<MP, 256>>>(hidden, pos);
    eprep_kernel<<<NP / 8, 256>>>(emb);
    gemm_mma<<<dim3(NP / BN, MP / BM), 256, DSMEM_BYTES>>>(out);
}